// round 12
// baseline (speedup 1.0000x reference)
#include <cuda_runtime.h>
#include <cstdint>
#include <cstddef>

// ---------------- problem dims ----------------
static constexpr int Mdim = 8192;   // B*T
static constexpr int Ndim = 1024;   // codebook rows
static constexpr int Kdim = 512;    // D

// ---------------- tiling (R5-proven shape, int8 payload) ----------------
static constexpr int MT = 128;
static constexpr int NT = 128;
static constexpr int KC = 128;           // K elems per chunk (128 int8 = 128B rows)
static constexpr int NCHUNK = Kdim / KC; // 4
static constexpr int THREADS = 256;      // 8 warps: 4 (M) x 2 (N), 32x64 each
static constexpr int STAGES = 3;
static constexpr int STAGE_BYTES = 32768;             // A 16K | B 16K
static constexpr int SM_TOTAL = STAGES * STAGE_BYTES; // 96 KB -> 2 CTAs/SM

__device__ float g_xsq[Mdim];
__device__ float g_csq[Ndim];
__device__ float g_sx[Mdim];             // per-row dequant scale for x
__device__ float g_sc[Ndim];             // per-row dequant scale for codebook
__device__ int8_t g_xi[(size_t)Mdim * Kdim];   // 4 MB
__device__ int8_t g_ci[(size_t)Ndim * Kdim];   // 0.5 MB

// ---------------- helpers ----------------
__device__ __forceinline__ uint32_t smem_u32(const void* p) {
    uint32_t a;
    asm("{ .reg .u64 t; cvta.to.shared.u64 t, %1; cvt.u32.u64 %0, t; }"
        : "=r"(a) : "l"(p));
    return a;
}
#define SW128(o) ((o) ^ (((o) >> 3) & 0x70))

__device__ __forceinline__ void cp16(uint32_t dst, const void* src) {
    asm volatile("cp.async.cg.shared.global [%0], [%1], 16;"
                 :: "r"(dst), "l"(src) : "memory");
}
#define CP_COMMIT() asm volatile("cp.async.commit_group;" ::: "memory")
#define CP_WAIT(n)  asm volatile("cp.async.wait_group %0;" :: "n"(n) : "memory")

__device__ __forceinline__ void ldsm_x4(uint32_t* r, uint32_t addr) {
    asm volatile("ldmatrix.sync.aligned.m8n8.x4.shared.b16 {%0,%1,%2,%3}, [%4];"
                 : "=r"(r[0]), "=r"(r[1]), "=r"(r[2]), "=r"(r[3]) : "r"(addr));
}

__device__ __forceinline__ void mma_s8(int* c, const uint32_t* a,
                                       uint32_t b0, uint32_t b1) {
    asm volatile(
        "mma.sync.aligned.m16n8k32.row.col.s32.s8.s8.s32 "
        "{%0,%1,%2,%3}, {%4,%5,%6,%7}, {%8,%9}, {%0,%1,%2,%3};"
        : "+r"(c[0]), "+r"(c[1]), "+r"(c[2]), "+r"(c[3])
        : "r"(a[0]), "r"(a[1]), "r"(a[2]), "r"(a[3]), "r"(b0), "r"(b1));
}

__device__ __forceinline__ uint32_t quant4(float4 v, float inv) {
    int b0 = __float2int_rn(v.x * inv);
    int b1 = __float2int_rn(v.y * inv);
    int b2 = __float2int_rn(v.z * inv);
    int b3 = __float2int_rn(v.w * inv);
    b0 = max(-127, min(127, b0));
    b1 = max(-127, min(127, b1));
    b2 = max(-127, min(127, b2));
    b3 = max(-127, min(127, b3));
    return (uint32_t)(b0 & 255) | ((uint32_t)(b1 & 255) << 8)
         | ((uint32_t)(b2 & 255) << 16) | ((uint32_t)(b3 & 255) << 24);
}

// ------- prep: row absmax + sumsq (pass1), quantize int8 (pass2) -------
// One warp per 16-row block. Lane l owns rows r0=blk*16+(l>>2), r0+8 at
// byte cols (l&3)*4 (+16) per k32 block.
__global__ void __launch_bounds__(256) prep_kernel(const float* __restrict__ x,
                                                   const float* __restrict__ cb) {
    int wblk = blockIdx.x * 8 + (threadIdx.x >> 5);
    int lane = threadIdx.x & 31;
    const float* src;
    int8_t* dsti;
    float *norm, *scl;
    int blk;
    if (wblk < Mdim / 16) {
        blk = wblk; src = x; dsti = g_xi; norm = g_xsq; scl = g_sx;
    } else {
        blk = wblk - Mdim / 16;
        if (blk >= Ndim / 16) return;
        src = cb; dsti = g_ci; norm = g_csq; scl = g_sc;
    }
    const int r0 = blk * 16 + (lane >> 2);
    const int c0 = (lane & 3) * 4;
    const float* row0 = src + (size_t)r0 * Kdim;
    const float* row1 = row0 + (size_t)8 * Kdim;
    float s0 = 0.f, s1 = 0.f, m0 = 0.f, m1 = 0.f;
    #pragma unroll 4
    for (int kb = 0; kb < Kdim / 32; kb++) {
        const int c = kb * 32 + c0;
        float4 a00 = *reinterpret_cast<const float4*>(row0 + c);
        float4 a01 = *reinterpret_cast<const float4*>(row0 + c + 16);
        float4 a10 = *reinterpret_cast<const float4*>(row1 + c);
        float4 a11 = *reinterpret_cast<const float4*>(row1 + c + 16);
        s0 += a00.x*a00.x + a00.y*a00.y + a00.z*a00.z + a00.w*a00.w
            + a01.x*a01.x + a01.y*a01.y + a01.z*a01.z + a01.w*a01.w;
        s1 += a10.x*a10.x + a10.y*a10.y + a10.z*a10.z + a10.w*a10.w
            + a11.x*a11.x + a11.y*a11.y + a11.z*a11.z + a11.w*a11.w;
        m0 = fmaxf(m0, fmaxf(fmaxf(fabsf(a00.x), fabsf(a00.y)),
                             fmaxf(fabsf(a00.z), fabsf(a00.w))));
        m0 = fmaxf(m0, fmaxf(fmaxf(fabsf(a01.x), fabsf(a01.y)),
                             fmaxf(fabsf(a01.z), fabsf(a01.w))));
        m1 = fmaxf(m1, fmaxf(fmaxf(fabsf(a10.x), fabsf(a10.y)),
                             fmaxf(fabsf(a10.z), fabsf(a10.w))));
        m1 = fmaxf(m1, fmaxf(fmaxf(fabsf(a11.x), fabsf(a11.y)),
                             fmaxf(fabsf(a11.z), fabsf(a11.w))));
    }
    #pragma unroll
    for (int o = 1; o <= 2; o <<= 1) {
        s0 += __shfl_xor_sync(0xffffffffu, s0, o);
        s1 += __shfl_xor_sync(0xffffffffu, s1, o);
        m0 = fmaxf(m0, __shfl_xor_sync(0xffffffffu, m0, o));
        m1 = fmaxf(m1, __shfl_xor_sync(0xffffffffu, m1, o));
    }
    const float inv0 = (m0 > 0.f) ? 127.f / m0 : 0.f;
    const float inv1 = (m1 > 0.f) ? 127.f / m1 : 0.f;
    if ((lane & 3) == 0) {
        norm[r0] = s0;     norm[r0 + 8] = s1;
        scl[r0]  = m0 / 127.f;  scl[r0 + 8] = m1 / 127.f;
    }
    // pass 2: quantize (re-reads hit L2)
    int8_t* d0 = dsti + (size_t)r0 * Kdim;
    int8_t* d1 = d0 + (size_t)8 * Kdim;
    #pragma unroll 4
    for (int kb = 0; kb < Kdim / 32; kb++) {
        const int c = kb * 32 + c0;
        float4 a00 = *reinterpret_cast<const float4*>(row0 + c);
        float4 a01 = *reinterpret_cast<const float4*>(row0 + c + 16);
        float4 a10 = *reinterpret_cast<const float4*>(row1 + c);
        float4 a11 = *reinterpret_cast<const float4*>(row1 + c + 16);
        *reinterpret_cast<uint32_t*>(d0 + c)      = quant4(a00, inv0);
        *reinterpret_cast<uint32_t*>(d0 + c + 16) = quant4(a01, inv0);
        *reinterpret_cast<uint32_t*>(d1 + c)      = quant4(a10, inv1);
        *reinterpret_cast<uint32_t*>(d1 + c + 16) = quant4(a11, inv1);
    }
}

// ------- chunk loader: 128x128B A + 128x128B B rows, SW128 -------
__device__ __forceinline__ void load_chunk(int m0, int n0, int c,
                                           uint32_t stg, int tid) {
    const int8_t* xa  = g_xi + (size_t)m0 * Kdim + c * KC;
    const int8_t* cbp = g_ci + (size_t)n0 * Kdim + c * KC;
    #pragma unroll
    for (int t = 0; t < 4; t++) {
        int i  = tid + t * THREADS;   // 0..1023
        int r  = i >> 3;              // row 0..127
        int j4 = i & 7;               // 16B piece within 128B row
        uint32_t off = SW128((uint32_t)(r * 128 + j4 * 16));
        cp16(stg + off,          xa  + (size_t)r * Kdim + j4 * 16);
        cp16(stg + 16384u + off, cbp + (size_t)r * Kdim + j4 * 16);
    }
}

// ---------------- GEMM + fused dequant epilogue ----------------
__global__ void __launch_bounds__(THREADS, 2)
gemm_kernel(const float* __restrict__ precision, float* __restrict__ out) {
    extern __shared__ char smem[];
    const uint32_t sb = smem_u32(smem);
    const int tid  = threadIdx.x;
    const int lane = tid & 31;
    const int w    = tid >> 5;
    const int wm   = w >> 1;          // 0..3
    const int wn   = w & 1;           // 0..1
    const int m0 = blockIdx.y * MT;
    const int n0 = blockIdx.x * NT;

    // ldmatrix offsets (bytes within 128B-row tiles, pre-swizzle) — the
    // m16n8k32 s8 fragments map to the SAME x4 addresses as bf16 m16n8k16.
    const int aRow0 = wm * 32 + (lane & 15);
    const int aColB = ((lane >> 4) & 1) * 16;
    const int bRow0 = wn * 64 + (lane & 7) + ((lane >> 4) & 1) * 8;
    const int bColB = ((lane >> 3) & 1) * 16;

    int acc[2][8][4];
    #pragma unroll
    for (int mf = 0; mf < 2; mf++)
        #pragma unroll
        for (int nf = 0; nf < 8; nf++)
            #pragma unroll
            for (int q = 0; q < 4; q++) acc[mf][nf][q] = 0;

    // prologue: 2 chunks in flight
    load_chunk(m0, n0, 0, sb + 0 * STAGE_BYTES, tid); CP_COMMIT();
    load_chunk(m0, n0, 1, sb + 1 * STAGE_BYTES, tid); CP_COMMIT();

    #pragma unroll 1
    for (int c = 0; c < NCHUNK; c++) {
        if (c < NCHUNK - 1) { CP_WAIT(1); } else { CP_WAIT(0); }
        __syncthreads();
        if (c + 2 < NCHUNK) {
            load_chunk(m0, n0, c + 2, sb + ((c + 2) % 3) * STAGE_BYTES, tid);
            CP_COMMIT();
        }
        const uint32_t sA = sb + (c % 3) * STAGE_BYTES;
        const uint32_t sB = sA + 16384u;
        #pragma unroll
        for (int ks = 0; ks < 4; ks++) {            // k32 steps; 32B each
            uint32_t af[2][4];
            #pragma unroll
            for (int mf = 0; mf < 2; mf++)
                ldsm_x4(af[mf], sA + SW128((uint32_t)((aRow0 + mf * 16) * 128
                                                      + ks * 32 + aColB)));
            uint32_t bf[4][4];
            #pragma unroll
            for (int nf2 = 0; nf2 < 4; nf2++)
                ldsm_x4(bf[nf2], sB + SW128((uint32_t)((bRow0 + nf2 * 16) * 128
                                                       + ks * 32 + bColB)));
            #pragma unroll
            for (int mf = 0; mf < 2; mf++)
                #pragma unroll
                for (int nf = 0; nf < 8; nf++)
                    mma_s8(acc[mf][nf], af[mf],
                           bf[nf >> 1][(nf & 1) * 2],
                           bf[nf >> 1][(nf & 1) * 2 + 1]);
        }
    }

    // ---------------- epilogue: dequant + stage + coalesced store ---------
    __syncthreads();   // everyone done reading stage smem
    float* sE = reinterpret_cast<float*>(smem);   // [128][132]
    const int erow = wm * 32 + (lane >> 2);
    const int ecol = wn * 64 + (lane & 3) * 2;
    #pragma unroll
    for (int mf = 0; mf < 2; mf++) {
        const float sxa = 2.f * g_sx[m0 + erow + mf * 16];
        const float sxb = 2.f * g_sx[m0 + erow + mf * 16 + 8];
        #pragma unroll
        for (int nf = 0; nf < 8; nf++) {
            const float2 sc2 =
                *reinterpret_cast<const float2*>(&g_sc[n0 + ecol + nf * 8]);
            float2* p0 = reinterpret_cast<float2*>(
                &sE[(erow + mf * 16) * 132 + ecol + nf * 8]);
            float2* p1 = reinterpret_cast<float2*>(
                &sE[(erow + mf * 16 + 8) * 132 + ecol + nf * 8]);
            *p0 = make_float2(sxa * sc2.x * (float)acc[mf][nf][0],
                              sxa * sc2.y * (float)acc[mf][nf][1]);
            *p1 = make_float2(sxb * sc2.x * (float)acc[mf][nf][2],
                              sxb * sc2.y * (float)acc[mf][nf][3]);
        }
    }
    __syncthreads();

    const float prec = precision[0];
    const int cj = (tid & 31) * 4;              // col group of 4
    const float4 cs = *reinterpret_cast<const float4*>(&g_csq[n0 + cj]);
    #pragma unroll 4
    for (int it = 0; it < 16; it++) {
        const int r = (tid >> 5) + it * 8;      // 0..127
        const float xs = g_xsq[m0 + r];
        const float* sp = &sE[r * 132 + cj];
        float4 v;
        v.x = prec * (sp[0] - xs - cs.x);
        v.y = prec * (sp[1] - xs - cs.y);
        v.z = prec * (sp[2] - xs - cs.z);
        v.w = prec * (sp[3] - xs - cs.w);
        *reinterpret_cast<float4*>(&out[(size_t)(m0 + r) * Ndim + n0 + cj]) = v;
    }
}

// ---------------- launch ----------------
extern "C" void kernel_launch(void* const* d_in, const int* in_sizes, int n_in,
                              void* d_out, int out_size) {
    (void)in_sizes; (void)n_in; (void)out_size;
    const float* x    = (const float*)d_in[0];
    const float* cb   = (const float*)d_in[1];
    const float* prec = (const float*)d_in[2];
    float* out = (float*)d_out;

    cudaFuncSetAttribute(gemm_kernel,
                         cudaFuncAttributeMaxDynamicSharedMemorySize, SM_TOTAL);

    prep_kernel<<<(Mdim / 16 + Ndim / 16) / 8, 256>>>(x, cb);
    dim3 grid(Ndim / NT, Mdim / MT);   // (8, 64) = 512 CTAs
    gemm_kernel<<<grid, THREADS, SM_TOTAL>>>(prec, out);
}

// round 13
// speedup vs baseline: 2.6821x; 2.6821x over previous
#include <cuda_runtime.h>
#include <cuda_bf16.h>
#include <cstdint>
#include <cstddef>

// ---------------- problem dims ----------------
static constexpr int Mdim = 8192;   // B*T
static constexpr int Ndim = 1024;   // codebook rows
static constexpr int Kdim = 512;    // D

// ---------------- tiling: small CTAs, many barrier domains ----------------
static constexpr int MT = 64;
static constexpr int NT = 128;
static constexpr int KC = 64;            // K elems per chunk (64 bf16 = 128B rows)
static constexpr int NCHUNK = Kdim / KC; // 8
static constexpr int THREADS = 128;      // 4 warps: 2 (M) x 2 (N), 32x64 each
static constexpr int STAGES = 2;
static constexpr int STAGE_BYTES = 24576;             // A 8K | B 16K
static constexpr int SM_TOTAL = STAGES * STAGE_BYTES; // 48 KB -> 4 CTAs/SM

__device__ float g_xsq[Mdim];
__device__ float g_csq[Ndim];
__device__ __nv_bfloat16 g_xb[(size_t)Mdim * Kdim];   // 8 MB
__device__ __nv_bfloat16 g_cb[(size_t)Ndim * Kdim];   // 1 MB

// ---------------- helpers ----------------
__device__ __forceinline__ uint32_t smem_u32(const void* p) {
    uint32_t a;
    asm("{ .reg .u64 t; cvta.to.shared.u64 t, %1; cvt.u32.u64 %0, t; }"
        : "=r"(a) : "l"(p));
    return a;
}
#define SW128(o) ((o) ^ (((o) >> 3) & 0x70))

__device__ __forceinline__ uint32_t pack_bf16x2(float a, float b) {
    uint32_t r;
    asm("cvt.rn.bf16x2.f32 %0, %1, %2;" : "=r"(r) : "f"(b), "f"(a));
    return r;
}
__device__ __forceinline__ void cp16(uint32_t dst, const void* src) {
    asm volatile("cp.async.cg.shared.global [%0], [%1], 16;"
                 :: "r"(dst), "l"(src) : "memory");
}
#define CP_COMMIT() asm volatile("cp.async.commit_group;" ::: "memory")
#define CP_WAIT(n)  asm volatile("cp.async.wait_group %0;" :: "n"(n) : "memory")

__device__ __forceinline__ void ldsm_x4(uint32_t* r, uint32_t addr) {
    asm volatile("ldmatrix.sync.aligned.m8n8.x4.shared.b16 {%0,%1,%2,%3}, [%4];"
                 : "=r"(r[0]), "=r"(r[1]), "=r"(r[2]), "=r"(r[3]) : "r"(addr));
}
__device__ __forceinline__ void mma_bf16(float* c, const uint32_t* a,
                                         uint32_t b0, uint32_t b1) {
    asm volatile(
        "mma.sync.aligned.m16n8k16.row.col.f32.bf16.bf16.f32 "
        "{%0,%1,%2,%3}, {%4,%5,%6,%7}, {%8,%9}, {%0,%1,%2,%3};"
        : "+f"(c[0]), "+f"(c[1]), "+f"(c[2]), "+f"(c[3])
        : "r"(a[0]), "r"(a[1]), "r"(a[2]), "r"(a[3]), "r"(b0), "r"(b1));
}

// ------- prep: fp32 -> bf16 + row norms, one read pass (R5-proven) -------
__global__ void __launch_bounds__(256) prep_kernel(const float* __restrict__ x,
                                                   const float* __restrict__ cb) {
    int row  = blockIdx.x * 8 + (threadIdx.x >> 5);
    int lane = threadIdx.x & 31;
    const float4* src;
    __nv_bfloat16* dstb;
    float* dsts;
    if (row < Mdim) {
        src  = reinterpret_cast<const float4*>(x) + (size_t)row * (Kdim / 4);
        dstb = g_xb + (size_t)row * Kdim;
        dsts = g_xsq + row;
    } else if (row < Mdim + Ndim) {
        int r = row - Mdim;
        src  = reinterpret_cast<const float4*>(cb) + (size_t)r * (Kdim / 4);
        dstb = g_cb + (size_t)r * Kdim;
        dsts = g_csq + r;
    } else return;
    float s = 0.f;
    #pragma unroll
    for (int t = 0; t < Kdim / 128; t++) {
        int j = lane + t * 32;
        float4 v = src[j];
        s += v.x * v.x + v.y * v.y + v.z * v.z + v.w * v.w;
        uint2 pk;
        pk.x = pack_bf16x2(v.x, v.y);
        pk.y = pack_bf16x2(v.z, v.w);
        *reinterpret_cast<uint2*>(dstb + j * 4) = pk;
    }
    #pragma unroll
    for (int o = 16; o; o >>= 1) s += __shfl_xor_sync(0xffffffffu, s, o);
    if (lane == 0) *dsts = s;
}

// ------- chunk loader: 64x64bf16 A + 128x64bf16 B, SW128 -------
__device__ __forceinline__ void load_chunk(int m0, int n0, int c,
                                           uint32_t stg, int tid) {
    const __nv_bfloat16* xa  = g_xb + (size_t)m0 * Kdim + c * KC;
    const __nv_bfloat16* cbp = g_cb + (size_t)n0 * Kdim + c * KC;
    // A: 64 rows x 128B = 512 cp16
    #pragma unroll
    for (int t = 0; t < 4; t++) {
        int i  = tid + t * THREADS;   // 0..511
        int r  = i >> 3;              // row 0..63
        int j4 = i & 7;
        uint32_t off = SW128((uint32_t)(r * 128 + j4 * 16));
        cp16(stg + off, xa + (size_t)r * Kdim + j4 * 8);
    }
    // B: 128 rows x 128B = 1024 cp16, at +8KB
    #pragma unroll
    for (int t = 0; t < 8; t++) {
        int i  = tid + t * THREADS;   // 0..1023
        int r  = i >> 3;              // row 0..127
        int j4 = i & 7;
        uint32_t off = SW128((uint32_t)(r * 128 + j4 * 16));
        cp16(stg + 8192u + off, cbp + (size_t)r * Kdim + j4 * 8);
    }
}

// ---------------- GEMM + fused epilogue ----------------
__global__ void __launch_bounds__(THREADS, 4)
gemm_kernel(const float* __restrict__ precision, float* __restrict__ out) {
    extern __shared__ char smem[];
    const uint32_t sb = smem_u32(smem);
    const int tid  = threadIdx.x;
    const int lane = tid & 31;
    const int w    = tid >> 5;
    const int wm   = w >> 1;          // 0..1
    const int wn   = w & 1;           // 0..1
    const int m0 = blockIdx.y * MT;
    const int n0 = blockIdx.x * NT;

    // ldmatrix per-thread offsets (bytes within 128B-row tiles, pre-swizzle)
    const int aRow0 = wm * 32 + (lane & 15);
    const int aColB = ((lane >> 4) & 1) * 16;
    const int bRow0 = wn * 64 + (lane & 7) + ((lane >> 4) & 1) * 8;
    const int bColB = ((lane >> 3) & 1) * 16;

    float acc[2][8][4];
    #pragma unroll
    for (int mf = 0; mf < 2; mf++)
        #pragma unroll
        for (int nf = 0; nf < 8; nf++)
            #pragma unroll
            for (int q = 0; q < 4; q++) acc[mf][nf][q] = 0.f;

    // prologue: chunk 0 in flight
    load_chunk(m0, n0, 0, sb, tid); CP_COMMIT();

    #pragma unroll 1
    for (int c = 0; c < NCHUNK; c++) {
        CP_WAIT(0);
        __syncthreads();      // chunk c visible to all warps; old stage free
        if (c + 1 < NCHUNK) {
            load_chunk(m0, n0, c + 1, sb + ((c + 1) & 1) * STAGE_BYTES, tid);
            CP_COMMIT();
        }
        const uint32_t sA = sb + (c & 1) * STAGE_BYTES;
        const uint32_t sB = sA + 8192u;
        #pragma unroll
        for (int ks = 0; ks < 4; ks++) {            // k16 steps; 32B each
            uint32_t af[2][4];
            #pragma unroll
            for (int mf = 0; mf < 2; mf++)
                ldsm_x4(af[mf], sA + SW128((uint32_t)((aRow0 + mf * 16) * 128
                                                      + ks * 32 + aColB)));
            uint32_t bf[4][4];
            #pragma unroll
            for (int nf2 = 0; nf2 < 4; nf2++)
                ldsm_x4(bf[nf2], sB + SW128((uint32_t)((bRow0 + nf2 * 16) * 128
                                                       + ks * 32 + bColB)));
            #pragma unroll
            for (int mf = 0; mf < 2; mf++)
                #pragma unroll
                for (int nf = 0; nf < 8; nf++)
                    mma_bf16(acc[mf][nf], af[mf],
                             bf[nf >> 1][(nf & 1) * 2],
                             bf[nf >> 1][(nf & 1) * 2 + 1]);
        }
        __syncthreads();      // all warps done with stage c before next refill
    }

    // ---------------- epilogue ----------------
    float* sE = reinterpret_cast<float*>(smem);   // [64][132] = 33.8 KB
    const int erow = wm * 32 + (lane >> 2);
    const int ecol = wn * 64 + (lane & 3) * 2;
    #pragma unroll
    for (int mf = 0; mf < 2; mf++) {
        #pragma unroll
        for (int nf = 0; nf < 8; nf++) {
            float2* p0 = reinterpret_cast<float2*>(
                &sE[(erow + mf * 16) * 132 + ecol + nf * 8]);
            float2* p1 = reinterpret_cast<float2*>(
                &sE[(erow + mf * 16 + 8) * 132 + ecol + nf * 8]);
            *p0 = make_float2(acc[mf][nf][0], acc[mf][nf][1]);
            *p1 = make_float2(acc[mf][nf][2], acc[mf][nf][3]);
        }
    }
    __syncthreads();

    const float prec = precision[0];
    const int cj = (tid & 31) * 4;              // col group of 4 (128 cols)
    const float4 cs = *reinterpret_cast<const float4*>(&g_csq[n0 + cj]);
    #pragma unroll 4
    for (int it = 0; it < 16; it++) {
        const int r = (tid >> 5) + it * 4;      // 0..63
        const float xs = g_xsq[m0 + r];
        const float* sp = &sE[r * 132 + cj];
        float4 v;
        v.x = prec * (2.f * sp[0] - xs - cs.x);
        v.y = prec * (2.f * sp[1] - xs - cs.y);
        v.z = prec * (2.f * sp[2] - xs - cs.z);
        v.w = prec * (2.f * sp[3] - xs - cs.w);
        *reinterpret_cast<float4*>(&out[(size_t)(m0 + r) * Ndim + n0 + cj]) = v;
    }
}

// ---------------- launch ----------------
extern "C" void kernel_launch(void* const* d_in, const int* in_sizes, int n_in,
                              void* d_out, int out_size) {
    (void)in_sizes; (void)n_in; (void)out_size;
    const float* x    = (const float*)d_in[0];
    const float* cb   = (const float*)d_in[1];
    const float* prec = (const float*)d_in[2];
    float* out = (float*)d_out;

    cudaFuncSetAttribute(gemm_kernel,
                         cudaFuncAttributeMaxDynamicSharedMemorySize, SM_TOTAL);

    prep_kernel<<<(Mdim + Ndim) / 8, 256>>>(x, cb);
    dim3 grid(Ndim / NT, Mdim / MT);   // (8, 128) = 1024 CTAs
    gemm_kernel<<<grid, THREADS, SM_TOTAL>>>(prec, out);
}